// round 11
// baseline (speedup 1.0000x reference)
#include <cuda_runtime.h>
#include <cstdint>
#include <math.h>

// ===========================================================================
// Scratch (device globals; no allocation in kernel_launch)
// ===========================================================================
__device__ float g_feat1[2 * 512 * 4096];
__device__ float g_feat2[2 * 512 * 4096];
__device__ float g_q[2 * 64 * 4096];
__device__ float g_k[2 * 64 * 4096];
__device__ float g_v[2 * 512 * 4096];
__device__ float g_energy[2 * 4096 * 4096];
__device__ float g_sa_feat[2 * 512 * 4096];
__device__ float g_sc_feat[2 * 512 * 4096];
__device__ float g_sa_conv[2 * 512 * 4096];
__device__ float g_cam_e[2 * 512 * 512];
__device__ float g_scale[4 * 512];
__device__ float g_bias[4 * 512];
__device__ float g_xtf[2 * 2048 * 4096];        // tf32-rounded input
// repacked conv weights: [tap][ci][co], tf32-rounded
__device__ float g_wta[9 * 2048 * 512];
__device__ float g_wtc[9 * 2048 * 512];
__device__ float g_wt1[9 * 512 * 512];
__device__ float g_wt2[9 * 512 * 512];
// tf32-rounded 1x1 weights
__device__ float g_wqr[64 * 512];
__device__ float g_wkr[64 * 512];
__device__ float g_wvr[512 * 512];

// ===========================================================================
// Helpers
// ===========================================================================
__device__ __forceinline__ float tf32r(float x) {
    uint32_t u;
    asm("cvt.rna.tf32.f32 %0, %1;" : "=r"(u) : "f"(x));
    return __uint_as_float(u);
}

__device__ __forceinline__ uint32_t smem_u32(const void* p) {
    uint32_t a;
    asm("{ .reg .u64 t; cvta.to.shared.u64 t, %1; cvt.u32.u64 %0, t; }" : "=r"(a) : "l"(p));
    return a;
}

__device__ __forceinline__ void cp16(uint32_t dst, const float* src) {
    asm volatile("cp.async.ca.shared.global [%0], [%1], 16;" :: "r"(dst), "l"(src));
}
__device__ __forceinline__ void cp4z(uint32_t dst, const float* src, int sz) {
    asm volatile("cp.async.ca.shared.global [%0], [%1], 4, %2;" :: "r"(dst), "l"(src), "r"(sz));
}
#define CP_COMMIT() asm volatile("cp.async.commit_group;" ::: "memory")
#define CP_WAIT0()  asm volatile("cp.async.wait_group 0;" ::: "memory")
#define CP_WAIT1()  asm volatile("cp.async.wait_group 1;" ::: "memory")

#define MMA_TF32(c, a, b0_, b1_) \
    asm volatile("mma.sync.aligned.m16n8k8.row.col.f32.tf32.tf32.f32 " \
        "{%0,%1,%2,%3}, {%4,%5,%6,%7}, {%8,%9}, {%0,%1,%2,%3};" \
        : "+f"((c)[0]), "+f"((c)[1]), "+f"((c)[2]), "+f"((c)[3]) \
        : "r"((a)[0]), "r"((a)[1]), "r"((a)[2]), "r"((a)[3]), "r"(b0_), "r"(b1_))

// pads: k-major rows [k][128] padded to 136 floats; m/n-major rows [.][32] padded to 40.
#define PKM 136
#define PMK 40

// ===========================================================================
// Prep kernels
// ===========================================================================
__global__ void round_tf32_kernel(const float* __restrict__ in, float* __restrict__ o, int n) {
    int t = (blockIdx.x * 256 + threadIdx.x) * 4;
    if (t + 3 < n) {
        float4 v = *(const float4*)&in[t];
        v.x = tf32r(v.x); v.y = tf32r(v.y); v.z = tf32r(v.z); v.w = tf32r(v.w);
        *(float4*)&o[t] = v;
    } else {
        for (int i = t; i < n; i++) o[i] = tf32r(in[i]);
    }
}

// repack w[co][ci][tap] -> o[tap][ci][co], tf32-rounded. Grid (512/32, Cin/8).
__global__ void repack_w(const float* __restrict__ w, float* __restrict__ o, int Cin) {
    __shared__ float s[32][73];
    const int tid = threadIdx.x;
    const int co0 = blockIdx.x * 32;
    const int ci0 = blockIdx.y * 8;
#pragma unroll
    for (int i = 0; i < 9; i++) {
        int e = i * 256 + tid;
        int co = e / 72, r = e % 72;
        s[co][r] = tf32r(w[((size_t)(co0 + co) * Cin + ci0 + r / 9) * 9 + (r % 9)]);
    }
    __syncthreads();
#pragma unroll
    for (int i = 0; i < 9; i++) {
        int e = i * 256 + tid;
        int co = e & 31, f = e >> 5;     // f = 0..71
        int tap = f / 8, ci = f % 8;
        o[((size_t)tap * Cin + ci0 + ci) * 512 + co0 + co] = s[co][ci * 9 + tap];
    }
}

__global__ void fold_bn_kernel(
    const float* s0, const float* b0, const float* m0, const float* v0,
    const float* s1, const float* b1, const float* m1, const float* v1,
    const float* s2, const float* b2, const float* m2, const float* v2,
    const float* s3, const float* b3, const float* m3, const float* v3)
{
    const float* S[4] = {s0, s1, s2, s3};
    const float* B[4] = {b0, b1, b2, b3};
    const float* M[4] = {m0, m1, m2, m3};
    const float* V[4] = {v0, v1, v2, v3};
    int set = blockIdx.x;
    int c = threadIdx.x;
    float inv = rsqrtf(V[set][c] + 1e-5f) * S[set][c];
    g_scale[set * 512 + c] = inv;
    g_bias[set * 512 + c]  = B[set][c] - M[set][c] * inv;
}

// ===========================================================================
// MMA compute core: block tile 128m x 128n, KB=32. 8 warps = 4m x 2n.
// Warp tile 32m x 64n -> 2 m-frags x 8 n-frags of m16n8k8.
// AMK: A smem layout [m][k] (pad 40) else [k][m] (pad 136). BNK analogous.
// ===========================================================================
template <int AMK, int BNK>
__device__ __forceinline__ void mma_block(
    const float* __restrict__ As, const float* __restrict__ Bs,
    int wm, int wn, int group, int tig, float acc[2][8][4])
{
#pragma unroll
    for (int s = 0; s < 4; s++) {
        const int k8 = s * 8;
        uint32_t a[2][4];
#pragma unroll
        for (int fm = 0; fm < 2; fm++) {
            const int m0 = wm + fm * 16 + group;
            if (AMK) {
                const float* p = As + m0 * PMK + k8 + tig;
                a[fm][0] = __float_as_uint(p[0]);
                a[fm][1] = __float_as_uint(p[8 * PMK]);
                a[fm][2] = __float_as_uint(p[4]);
                a[fm][3] = __float_as_uint(p[8 * PMK + 4]);
            } else {
                const float* p = As + (k8 + tig) * PKM + m0;
                a[fm][0] = __float_as_uint(p[0]);
                a[fm][1] = __float_as_uint(p[8]);
                a[fm][2] = __float_as_uint(p[4 * PKM]);
                a[fm][3] = __float_as_uint(p[4 * PKM + 8]);
            }
        }
#pragma unroll
        for (int fn = 0; fn < 8; fn++) {
            const int n0 = wn + fn * 8 + group;
            uint32_t b0, b1;
            if (BNK) {
                const float* p = Bs + n0 * PMK + k8 + tig;
                b0 = __float_as_uint(p[0]);
                b1 = __float_as_uint(p[4]);
            } else {
                const float* p = Bs + (k8 + tig) * PKM + n0;
                b0 = __float_as_uint(p[0]);
                b1 = __float_as_uint(p[4 * PKM]);
            }
            MMA_TF32(acc[0][fn], a[0], b0, b1);
            MMA_TF32(acc[1][fn], a[1], b0, b1);
        }
    }
}

// ===========================================================================
// Implicit-GEMM 3x3 conv + BN + ReLU (+addend) (+tf32 round).
// Tile 128co x 128px (2 rows). Grid (4, 32, B). wT layout [tap][ci][co].
// ===========================================================================
__global__ __launch_bounds__(256, 2) void mma_conv(
    const float* __restrict__ x, const float* __restrict__ wT,
    int Cin, int bnset, const float* __restrict__ addend,
    float* __restrict__ out, int rnd)
{
    extern __shared__ float smf[];
    // layout: A0[32*136] A1 B0[32*136] B1
    const uint32_t sbase = smem_u32(smf);
    float* Abuf[2] = {smf, smf + 32 * PKM};
    float* Bbuf[2] = {smf + 2 * 32 * PKM, smf + 3 * 32 * PKM};
    const uint32_t sbA[2] = {sbase, sbase + 32 * PKM * 4};
    const uint32_t sbB[2] = {sbase + 2 * 32 * PKM * 4, sbase + 3 * 32 * PKM * 4};

    const int tid = threadIdx.x;
    const int warp = tid >> 5, lane = tid & 31;
    const int group = lane >> 2, tig = lane & 3;
    const int wm = (warp & 3) * 32, wn = (warp >> 2) * 64;
    const int coBase = blockIdx.x * 128;
    const int pixBase = blockIdx.y * 128;
    const int y0 = blockIdx.y * 2;
    const int bb = blockIdx.z;

    const float* xb = x + (size_t)bb * Cin * 4096;
    const int NKB = (Cin >> 5) * 9;

    // per-thread constant pieces of B staging
    const int nl = tid & 127;            // pixel within tile
    const int rb0 = tid >> 7;            // 0/1
    const int yy = nl >> 6, xx = nl & 63;
    // A staging constants
    const int cgA = tid & 31;
    const int ra0 = tid >> 5;            // 0..7

    float acc[2][8][4];
#pragma unroll
    for (int i = 0; i < 2; i++)
#pragma unroll
        for (int j = 0; j < 8; j++)
#pragma unroll
            for (int c = 0; c < 4; c++) acc[i][j][c] = 0.f;

    auto stage = [&](int buf, int kb) {
        const int cib = kb / 9;
        const int tap = kb - cib * 9;
        const int ci0 = cib << 5;
        const int dy = tap / 3 - 1;
        const int dx = tap - (tap / 3) * 3 - 1;
        // A: [k=ci][m=co] from wT[tap][ci][co] (contiguous in co)
        const float* wrow = wT + ((size_t)tap * Cin + ci0) * 512 + coBase;
#pragma unroll
        for (int i = 0; i < 4; i++) {
            const int row = ra0 + i * 8;
            cp16(sbA[buf] + (uint32_t)(row * PKM + cgA * 4) * 4, wrow + (size_t)row * 512 + cgA * 4);
        }
        // B: [k=ci][n=px] im2col, scalar zfill
        const int ys = y0 + yy + dy;
        const int xs = xx + dx;
        const int ok = ((unsigned)ys < 64u && (unsigned)xs < 64u) ? 4 : 0;
        const int soff = ok ? ((ys << 6) + xs) : 0;
        const float* bsrc = xb + ((size_t)ci0 << 12) + soff;
#pragma unroll
        for (int i = 0; i < 16; i++) {
            const int row = rb0 + i * 2;
            cp4z(sbB[buf] + (uint32_t)(row * PKM + nl) * 4, bsrc + ((size_t)row << 12), ok);
        }
    };

    stage(0, 0);
    CP_COMMIT();
    for (int kb = 0; kb < NKB; kb++) {
        if (kb + 1 < NKB) {
            stage((kb + 1) & 1, kb + 1);
            CP_COMMIT();
            CP_WAIT1();
        } else {
            CP_WAIT0();
        }
        __syncthreads();
        mma_block<0, 0>(Abuf[kb & 1], Bbuf[kb & 1], wm, wn, group, tig, acc);
        __syncthreads();
    }

    // epilogue: BN + ReLU (+addend) (+round)
#pragma unroll
    for (int fm = 0; fm < 2; fm++) {
#pragma unroll
        for (int half = 0; half < 2; half++) {
            const int co = coBase + wm + fm * 16 + group + half * 8;
            const float sc = g_scale[bnset * 512 + co];
            const float bi = g_bias[bnset * 512 + co];
            float* orow = out + (((size_t)(bb * 512 + co)) << 12) + pixBase;
            const float* arow = addend ? addend + (((size_t)(bb * 512 + co)) << 12) + pixBase : nullptr;
#pragma unroll
            for (int fn = 0; fn < 8; fn++) {
                const int n = wn + fn * 8 + tig * 2;
                float v0 = fmaxf(acc[fm][fn][half * 2 + 0] * sc + bi, 0.f);
                float v1 = fmaxf(acc[fm][fn][half * 2 + 1] * sc + bi, 0.f);
                if (rnd) { v0 = tf32r(v0); v1 = tf32r(v1); }
                if (arow) { v0 += arow[n]; v1 += arow[n + 1]; }
                float2 st = {v0, v1};
                *(float2*)&orow[n] = st;
            }
        }
    }
}

// ===========================================================================
// GEMM: D[m][n] = sum_k a(m,k) b(n,k).  Tile 128x128, KB=32.
//   AMK=1: A[m][k] global row-major (stage [m][k] pad40); AMK=0: A[k][m] (stage [k][m] pad136)
//   BNK=1: B[n][k]; BNK=0: B[k][n]
//   EP: 0 none | 1 +bias[m] | 2 gamma*acc+add | 3 qk split (A rows<64: wq->C, else wk->C2)
//   RND: round output to tf32
// ===========================================================================
template <int AMK, int BNK, int EP, int RND>
__global__ __launch_bounds__(256, 2) void mma_gemm(
    const float* __restrict__ A, const float* __restrict__ Bm, float* __restrict__ C,
    int lda, int ldb, int ldc, int K,
    long sA, long sB, long sC,
    const float* __restrict__ A2, const float* __restrict__ bias, const float* __restrict__ bias2,
    const float* __restrict__ gamma, const float* __restrict__ add, long sAdd,
    float* __restrict__ C2, long sC2)
{
    extern __shared__ float smf[];
    constexpr int ASf = AMK ? 128 * PMK : 32 * PKM;
    constexpr int BSf = BNK ? 128 * PMK : 32 * PKM;
    const uint32_t sbase = smem_u32(smf);
    float* Abuf[2] = {smf, smf + ASf};
    float* Bbuf[2] = {smf + 2 * ASf, smf + 2 * ASf + BSf};
    const uint32_t sbA[2] = {sbase, sbase + ASf * 4};
    const uint32_t sbB[2] = {sbase + 2 * ASf * 4, sbase + (2 * ASf + BSf) * 4};

    const int tid = threadIdx.x;
    const int warp = tid >> 5, lane = tid & 31;
    const int group = lane >> 2, tig = lane & 3;
    const int wm = (warp & 3) * 32, wn = (warp >> 2) * 64;
    const int mBase = blockIdx.x * 128;
    const int nBase = blockIdx.y * 128;
    const int bb = blockIdx.z;

    const float* Ag = A + (size_t)bb * sA;
    const float* Bg = Bm + (size_t)bb * sB;
    const int NKB = K >> 5;

    float acc[2][8][4];
#pragma unroll
    for (int i = 0; i < 2; i++)
#pragma unroll
        for (int j = 0; j < 8; j++)
#pragma unroll
            for (int c = 0; c < 4; c++) acc[i][j][c] = 0.f;

    auto stage = [&](int buf, int kb) {
        const int k0 = kb << 5;
        if (AMK) {
            const int row = tid >> 3, cg = tid & 7;   // 4 iters: rows +32
#pragma unroll
            for (int i = 0; i < 4; i++) {
                const int r = row + i * 32;
                const float* src;
                if (EP == 3)
                    src = (r < 64 ? A + (size_t)r * lda : A2 + (size_t)(r - 64) * lda) + k0 + cg * 4;
                else
                    src = Ag + (size_t)(mBase + r) * lda + k0 + cg * 4;
                cp16(sbA[buf] + (uint32_t)(r * PMK + cg * 4) * 4, src);
            }
        } else {
            const int row = tid >> 5, cg = tid & 31;  // 4 iters: rows +8
#pragma unroll
            for (int i = 0; i < 4; i++) {
                const int r = row + i * 8;
                cp16(sbA[buf] + (uint32_t)(r * PKM + cg * 4) * 4,
                     Ag + (size_t)(k0 + r) * lda + mBase + cg * 4);
            }
        }
        if (BNK) {
            const int row = tid >> 3, cg = tid & 7;
#pragma unroll
            for (int i = 0; i < 4; i++) {
                const int r = row + i * 32;
                cp16(sbB[buf] + (uint32_t)(r * PMK + cg * 4) * 4,
                     Bg + (size_t)(nBase + r) * ldb + k0 + cg * 4);
            }
        } else {
            const int row = tid >> 5, cg = tid & 31;
#pragma unroll
            for (int i = 0; i < 4; i++) {
                const int r = row + i * 8;
                cp16(sbB[buf] + (uint32_t)(r * PKM + cg * 4) * 4,
                     Bg + (size_t)(k0 + r) * ldb + nBase + cg * 4);
            }
        }
    };

    stage(0, 0);
    CP_COMMIT();
    for (int kb = 0; kb < NKB; kb++) {
        if (kb + 1 < NKB) {
            stage((kb + 1) & 1, kb + 1);
            CP_COMMIT();
            CP_WAIT1();
        } else {
            CP_WAIT0();
        }
        __syncthreads();
        mma_block<AMK, BNK>(Abuf[kb & 1], Bbuf[kb & 1], wm, wn, group, tig, acc);
        __syncthreads();
    }

    // epilogue
    const float gv = (EP == 2) ? __ldg(&gamma[0]) : 0.f;
#pragma unroll
    for (int fm = 0; fm < 2; fm++) {
#pragma unroll
        for (int half = 0; half < 2; half++) {
            const int m = mBase + wm + fm * 16 + group + half * 8;
            float bv = 0.f;
            float* dst;
            if (EP == 3) {
                bv = (m < 64) ? __ldg(&bias[m]) : __ldg(&bias2[m - 64]);
                dst = (m < 64) ? C + (size_t)bb * sC + (size_t)m * ldc
                               : C2 + (size_t)bb * sC2 + (size_t)(m - 64) * ldc;
            } else {
                if (EP == 1) bv = __ldg(&bias[m]);
                dst = C + (size_t)bb * sC + (size_t)m * ldc;
            }
            const float* ap = (EP == 2) ? add + (size_t)bb * sAdd + (size_t)m * ldc : nullptr;
#pragma unroll
            for (int fn = 0; fn < 8; fn++) {
                const int n = nBase + wn + fn * 8 + tig * 2;
                float v0 = acc[fm][fn][half * 2 + 0];
                float v1 = acc[fm][fn][half * 2 + 1];
                if (EP == 1 || EP == 3) { v0 += bv; v1 += bv; }
                if (EP == 2) {
                    const float2 a2v = *(const float2*)&ap[n];
                    v0 = gv * v0 + a2v.x;
                    v1 = gv * v1 + a2v.y;
                }
                if (RND) { v0 = tf32r(v0); v1 = tf32r(v1); }
                float2 st = {v0, v1};
                *(float2*)&dst[n] = st;
            }
        }
    }
}

// ===========================================================================
// Softmaxes (attn outputs rounded to tf32 — they feed GEMMs)
// ===========================================================================
__global__ void softmax4096_kernel(float* __restrict__ e)
{
    float* p = e + (size_t)blockIdx.x * 4096;
    const int tid = threadIdx.x;
    float4 v[4];
    float mx = -1e30f;
#pragma unroll
    for (int i = 0; i < 4; i++) {
        v[i] = *(const float4*)&p[i * 1024 + tid * 4];
        mx = fmaxf(mx, fmaxf(fmaxf(v[i].x, v[i].y), fmaxf(v[i].z, v[i].w)));
    }
    __shared__ float red[8];
#pragma unroll
    for (int off = 16; off; off >>= 1) mx = fmaxf(mx, __shfl_xor_sync(0xffffffffu, mx, off));
    if ((tid & 31) == 0) red[tid >> 5] = mx;
    __syncthreads();
    mx = red[0];
#pragma unroll
    for (int i = 1; i < 8; i++) mx = fmaxf(mx, red[i]);
    __syncthreads();
    float s = 0.f;
#pragma unroll
    for (int i = 0; i < 4; i++) {
        v[i].x = __expf(v[i].x - mx); v[i].y = __expf(v[i].y - mx);
        v[i].z = __expf(v[i].z - mx); v[i].w = __expf(v[i].w - mx);
        s += v[i].x + v[i].y + v[i].z + v[i].w;
    }
#pragma unroll
    for (int off = 16; off; off >>= 1) s += __shfl_xor_sync(0xffffffffu, s, off);
    if ((tid & 31) == 0) red[tid >> 5] = s;
    __syncthreads();
    s = 0.f;
#pragma unroll
    for (int i = 0; i < 8; i++) s += red[i];
    const float inv = 1.f / s;
#pragma unroll
    for (int i = 0; i < 4; i++) {
        v[i].x = tf32r(v[i].x * inv); v[i].y = tf32r(v[i].y * inv);
        v[i].z = tf32r(v[i].z * inv); v[i].w = tf32r(v[i].w * inv);
        *(float4*)&p[i * 1024 + tid * 4] = v[i];
    }
}

__global__ void softmax512_cam_kernel(float* __restrict__ e)
{
    float* p = e + (size_t)blockIdx.x * 512;
    const int tid = threadIdx.x;
    float4 v = *(const float4*)&p[tid * 4];
    float mn = fminf(fminf(v.x, v.y), fminf(v.z, v.w));
    __shared__ float red[4];
#pragma unroll
    for (int off = 16; off; off >>= 1) mn = fminf(mn, __shfl_xor_sync(0xffffffffu, mn, off));
    if ((tid & 31) == 0) red[tid >> 5] = mn;
    __syncthreads();
    mn = fminf(fminf(red[0], red[1]), fminf(red[2], red[3]));
    __syncthreads();
    v.x = __expf(mn - v.x); v.y = __expf(mn - v.y);
    v.z = __expf(mn - v.z); v.w = __expf(mn - v.w);
    float s = v.x + v.y + v.z + v.w;
#pragma unroll
    for (int off = 16; off; off >>= 1) s += __shfl_xor_sync(0xffffffffu, s, off);
    if ((tid & 31) == 0) red[tid >> 5] = s;
    __syncthreads();
    s = red[0] + red[1] + red[2] + red[3];
    const float inv = 1.f / s;
    v.x = tf32r(v.x * inv); v.y = tf32r(v.y * inv);
    v.z = tf32r(v.z * inv); v.w = tf32r(v.w * inv);
    *(float4*)&p[tid * 4] = v;
}

// ===========================================================================
// Launch
// ===========================================================================
#define SM_CONV ((4 * 32 * PKM) * 4)
static inline int smem_gemm(int amk, int bnk) {
    int a = amk ? 128 * PMK : 32 * PKM;
    int b = bnk ? 128 * PMK : 32 * PKM;
    return (2 * a + 2 * b) * 4;
}

extern "C" void kernel_launch(void* const* d_in, const int* in_sizes, int n_in,
                              void* d_out, int out_size)
{
    (void)in_sizes; (void)n_in; (void)out_size;

    const float* x         = (const float*)d_in[0];
    const float* w5a       = (const float*)d_in[1];
    const float* w5c       = (const float*)d_in[6];
    const float* wq        = (const float*)d_in[11];
    const float* bq        = (const float*)d_in[12];
    const float* wk        = (const float*)d_in[13];
    const float* bk        = (const float*)d_in[14];
    const float* wv        = (const float*)d_in[15];
    const float* bv        = (const float*)d_in[16];
    const float* gamma_pam = (const float*)d_in[17];
    const float* gamma_cam = (const float*)d_in[18];
    const float* w51       = (const float*)d_in[19];
    const float* w52       = (const float*)d_in[24];
    float* out = (float*)d_out;

    float *feat1, *feat2, *q, *k, *v, *energy, *sa_feat, *sc_feat, *sa_conv, *cam_e;
    float *xtf, *wta, *wtc, *wt1, *wt2, *wqr, *wkr, *wvr;
    cudaGetSymbolAddress((void**)&feat1,   g_feat1);
    cudaGetSymbolAddress((void**)&feat2,   g_feat2);
    cudaGetSymbolAddress((void**)&q,       g_q);
    cudaGetSymbolAddress((void**)&k,       g_k);
    cudaGetSymbolAddress((void**)&v,       g_v);
    cudaGetSymbolAddress((void**)&energy,  g_energy);
    cudaGetSymbolAddress((void**)&sa_feat, g_sa_feat);
    cudaGetSymbolAddress((void**)&sc_feat, g_sc_feat);
    cudaGetSymbolAddress((void**)&sa_conv, g_sa_conv);
    cudaGetSymbolAddress((void**)&cam_e,   g_cam_e);
    cudaGetSymbolAddress((void**)&xtf,     g_xtf);
    cudaGetSymbolAddress((void**)&wta,     g_wta);
    cudaGetSymbolAddress((void**)&wtc,     g_wtc);
    cudaGetSymbolAddress((void**)&wt1,     g_wt1);
    cudaGetSymbolAddress((void**)&wt2,     g_wt2);
    cudaGetSymbolAddress((void**)&wqr,     g_wqr);
    cudaGetSymbolAddress((void**)&wkr,     g_wkr);
    cudaGetSymbolAddress((void**)&wvr,     g_wvr);

    // smem opt-in
    cudaFuncSetAttribute(mma_conv, cudaFuncAttributeMaxDynamicSharedMemorySize, SM_CONV);
    cudaFuncSetAttribute(mma_gemm<1,0,3,1>, cudaFuncAttributeMaxDynamicSharedMemorySize, smem_gemm(1,0));
    cudaFuncSetAttribute(mma_gemm<1,0,1,1>, cudaFuncAttributeMaxDynamicSharedMemorySize, smem_gemm(1,0));
    cudaFuncSetAttribute(mma_gemm<0,0,0,0>, cudaFuncAttributeMaxDynamicSharedMemorySize, smem_gemm(0,0));
    cudaFuncSetAttribute(mma_gemm<1,1,2,1>, cudaFuncAttributeMaxDynamicSharedMemorySize, smem_gemm(1,1));
    cudaFuncSetAttribute(mma_gemm<1,1,0,0>, cudaFuncAttributeMaxDynamicSharedMemorySize, smem_gemm(1,1));
    cudaFuncSetAttribute(mma_gemm<1,0,2,1>, cudaFuncAttributeMaxDynamicSharedMemorySize, smem_gemm(1,0));

    // 0) prep: round x + weights to tf32, repack conv weights, fold BN
    round_tf32_kernel<<<16384, 256>>>(x, xtf, 2 * 2048 * 4096);
    round_tf32_kernel<<<32, 256>>>(wq, wqr, 64 * 512);
    round_tf32_kernel<<<32, 256>>>(wk, wkr, 64 * 512);
    round_tf32_kernel<<<256, 256>>>(wv, wvr, 512 * 512);
    repack_w<<<dim3(16, 256), 256>>>(w5a, wta, 2048);
    repack_w<<<dim3(16, 256), 256>>>(w5c, wtc, 2048);
    repack_w<<<dim3(16, 64), 256>>>(w51, wt1, 512);
    repack_w<<<dim3(16, 64), 256>>>(w52, wt2, 512);
    fold_bn_kernel<<<4, 512>>>(
        (const float*)d_in[2],  (const float*)d_in[3],  (const float*)d_in[4],  (const float*)d_in[5],
        (const float*)d_in[7],  (const float*)d_in[8],  (const float*)d_in[9],  (const float*)d_in[10],
        (const float*)d_in[20], (const float*)d_in[21], (const float*)d_in[22], (const float*)d_in[23],
        (const float*)d_in[25], (const float*)d_in[26], (const float*)d_in[27], (const float*)d_in[28]);

    const dim3 cgrid(4, 32, 2);
    const long F = 512L * 4096;
    const long Q = 64L * 4096;
    const long E = 4096L * 4096;

    // 1) feat1 = CBR(x, w5a); feat2 = CBR(x, w5c)   (rounded for downstream GEMMs)
    mma_conv<<<cgrid, 256, SM_CONV>>>(xtf, wta, 2048, 0, nullptr, feat1, 1);
    mma_conv<<<cgrid, 256, SM_CONV>>>(xtf, wtc, 2048, 1, nullptr, feat2, 1);

    // 2) q,k stacked (M=128: rows<64 -> q, else k).  A=wq/wk [m][k], B=feat1 [k][n]
    mma_gemm<1,0,3,1><<<dim3(1, 32, 2), 256, smem_gemm(1,0)>>>(
        wqr, feat1, q, 512, 4096, 4096, 512, 0, F, Q,
        wkr, bq, bk, nullptr, nullptr, 0, k, Q);

    // 3) v = wv @ feat1 + bv
    mma_gemm<1,0,1,1><<<dim3(4, 32, 2), 256, smem_gemm(1,0)>>>(
        wvr, feat1, v, 512, 4096, 4096, 512, 0, F, F,
        nullptr, bv, nullptr, nullptr, nullptr, 0, nullptr, 0);

    // 4) energy[qpix][kpix] = sum_c q[c][qpix] k[c][kpix].  A KM, B KN, K=64
    mma_gemm<0,0,0,0><<<dim3(32, 32, 2), 256, smem_gemm(0,0)>>>(
        q, k, energy, 4096, 4096, 4096, 64, Q, Q, E,
        nullptr, nullptr, nullptr, nullptr, nullptr, 0, nullptr, 0);

    // 5) PAM softmax (rounds attn)
    softmax4096_kernel<<<8192, 256>>>(energy);

    // 6) sa_feat = gamma_pam * (v @ attn^T) + feat1.  A=v [m][k] MK, B=attn [n][k] NK
    mma_gemm<1,1,2,1><<<dim3(4, 32, 2), 256, smem_gemm(1,1)>>>(
        v, energy, sa_feat, 4096, 4096, 4096, 4096, F, E, F,
        nullptr, nullptr, nullptr, gamma_pam, feat1, F, nullptr, 0);

    // 7) CAM energy = feat2 @ feat2^T.  A MK, B NK, K=4096
    mma_gemm<1,1,0,0><<<dim3(4, 4, 2), 256, smem_gemm(1,1)>>>(
        feat2, feat2, cam_e, 4096, 4096, 512, 4096, F, F, 512L * 512,
        nullptr, nullptr, nullptr, nullptr, nullptr, 0, nullptr, 0);

    // 8) CAM softmax (rounds attn)
    softmax512_cam_kernel<<<1024, 128>>>(cam_e);

    // 9) sc_feat = gamma_cam * (attn @ feat2) + feat2.  A=attn [m][k] MK, B=feat2 [k][n] KN
    mma_gemm<1,0,2,1><<<dim3(4, 32, 2), 256, smem_gemm(1,0)>>>(
        cam_e, feat2, sc_feat, 512, 4096, 4096, 512, 512L * 512, F, F,
        nullptr, nullptr, nullptr, gamma_cam, feat2, F, nullptr, 0);

    // 10) sa_conv = CBR(sa_feat, w51);  out = CBR(sc_feat, w52) + sa_conv
    mma_conv<<<cgrid, 256, SM_CONV>>>(sa_feat, wt1, 512, 2, nullptr, sa_conv, 0);
    mma_conv<<<cgrid, 256, SM_CONV>>>(sc_feat, wt2, 512, 3, sa_conv, out, 0);
}

// round 13
// speedup vs baseline: 2.0468x; 2.0468x over previous
#include <cuda_runtime.h>
#include <cuda_fp16.h>
#include <cstdint>
#include <math.h>

// ===========================================================================
// Globals
// ===========================================================================
__device__ __half g_feat1h[2 * 512 * 4096];
__device__ __half g_feat2h[2 * 512 * 4096];
__device__ __half g_qh[2 * 64 * 4096];
__device__ __half g_kh[2 * 64 * 4096];
__device__ __half g_vh[2 * 512 * 4096];
__device__ __half g_attnh[2 * 4096 * 4096];
__device__ __half g_camh[2 * 512 * 512];
__device__ float  g_energy[2 * 4096 * 4096];
__device__ float  g_cam[2 * 512 * 512];
__device__ float  g_saf[2 * 512 * 4096];
__device__ float  g_scf[2 * 512 * 4096];
__device__ float  g_sacv[2 * 512 * 4096];
__device__ float  g_scale[4 * 512];
__device__ float  g_bias[4 * 512];
__device__ __half g_wa[9 * 512 * 2048];
__device__ __half g_wc[9 * 512 * 2048];
__device__ __half g_w1[9 * 512 * 512];
__device__ __half g_w2[9 * 512 * 512];
__device__ __half g_wqh[64 * 512];
__device__ __half g_wkh[64 * 512];
__device__ __half g_wvh[512 * 512];

// ===========================================================================
// Helpers
// ===========================================================================
__device__ __forceinline__ uint32_t smem_u32(const void* p) {
    uint32_t a;
    asm("{ .reg .u64 t; cvta.to.shared.u64 t, %1; cvt.u32.u64 %0, t; }" : "=r"(a) : "l"(p));
    return a;
}
__device__ __forceinline__ void cp16(uint32_t dst, const void* src) {
    asm volatile("cp.async.ca.shared.global [%0], [%1], 16;" :: "r"(dst), "l"(src));
}
#define CP_COMMIT() asm volatile("cp.async.commit_group;" ::: "memory")
#define CP_WAIT0()  asm volatile("cp.async.wait_group 0;" ::: "memory")
#define CP_WAIT1()  asm volatile("cp.async.wait_group 1;" ::: "memory")

#define LDSM_X4(r, a) \
    asm volatile("ldmatrix.sync.aligned.m8n8.x4.shared.b16 {%0,%1,%2,%3}, [%4];" \
        : "=r"((r)[0]), "=r"((r)[1]), "=r"((r)[2]), "=r"((r)[3]) : "r"(a))
#define LDSM_X4T(r, a) \
    asm volatile("ldmatrix.sync.aligned.m8n8.x4.trans.shared.b16 {%0,%1,%2,%3}, [%4];" \
        : "=r"((r)[0]), "=r"((r)[1]), "=r"((r)[2]), "=r"((r)[3]) : "r"(a))
#define MMA_F16(c, a, b0_, b1_) \
    asm volatile("mma.sync.aligned.m16n8k16.row.col.f32.f16.f16.f32 " \
        "{%0,%1,%2,%3},{%4,%5,%6,%7},{%8,%9},{%0,%1,%2,%3};" \
        : "+f"((c)[0]), "+f"((c)[1]), "+f"((c)[2]), "+f"((c)[3]) \
        : "r"((a)[0]), "r"((a)[1]), "r"((a)[2]), "r"((a)[3]), "r"(b0_), "r"(b1_))

// smem pitches in halves: [.][32] rows pad 40; [k][128] rows pad 136
#define PMK 40
#define PKM 136

// ===========================================================================
// fp16 MMA core: tile 128m x 128n, KB=32. 8 warps = 4m x 2n, warp 32x64.
// AL: 0 = smem [m][PMK], 1 = smem [k][PKM] (trans ldmatrix). BL analogous.
// ===========================================================================
template <int AL, int BL>
__device__ __forceinline__ void mma_core(
    uint32_t aB, uint32_t bB, int wm, int wn, int lane, float (&acc)[2][8][4])
{
    const int w = lane & 7, q = lane >> 3;
#pragma unroll
    for (int s = 0; s < 2; s++) {
        const int k16 = s * 16;
        uint32_t A[2][4];
#pragma unroll
        for (int fm = 0; fm < 2; fm++) {
            const int m0 = wm + fm * 16;
            if (AL == 0) {
                LDSM_X4(A[fm], aB + (uint32_t)((m0 + (lane & 15)) * PMK + k16 + (lane >> 4) * 8) * 2);
            } else {
                LDSM_X4T(A[fm], aB + (uint32_t)((k16 + (q >> 1) * 8 + w) * PKM + m0 + (q & 1) * 8) * 2);
            }
        }
        uint32_t B[8][2];
#pragma unroll
        for (int g = 0; g < 4; g++) {
            uint32_t r[4];
            const int n0 = wn + g * 16;
            if (BL == 0) {
                LDSM_X4(r, bB + (uint32_t)((n0 + (q >> 1) * 8 + w) * PMK + k16 + (q & 1) * 8) * 2);
            } else {
                LDSM_X4T(r, bB + (uint32_t)((k16 + (q & 1) * 8 + w) * PKM + n0 + (q >> 1) * 8) * 2);
            }
            B[g * 2][0] = r[0]; B[g * 2][1] = r[1];
            B[g * 2 + 1][0] = r[2]; B[g * 2 + 1][1] = r[3];
        }
#pragma unroll
        for (int fm = 0; fm < 2; fm++)
#pragma unroll
            for (int fn = 0; fn < 8; fn++)
                MMA_F16(acc[fm][fn], A[fm], B[fn][0], B[fn][1]);
    }
}

// ===========================================================================
// Prep kernels
// ===========================================================================
__global__ void f2h_kernel(const float* __restrict__ in, __half* __restrict__ o, int n) {
    int t = blockIdx.x * 256 + threadIdx.x;
    if (t < n) o[t] = __float2half(in[t]);
}

// repack w[co][ci][tap] (f32) -> o[tap][co][ci] (half). Grid (16, Cin/8), 256 thr.
__global__ void repack_wh(const float* __restrict__ w, __half* __restrict__ o, int Cin) {
    __shared__ float s[32][73];
    const int tid = threadIdx.x;
    const int co0 = blockIdx.x * 32;
    const int ci0 = blockIdx.y * 8;
#pragma unroll
    for (int i = 0; i < 9; i++) {
        int e = i * 256 + tid;
        int co = e / 72, r = e % 72;
        s[co][r] = w[((size_t)(co0 + co) * Cin + ci0 + r / 9) * 9 + (r % 9)];
    }
    __syncthreads();
    const int ci = tid & 7, co = tid >> 3;
#pragma unroll
    for (int tap = 0; tap < 9; tap++)
        o[((size_t)tap * 512 + co0 + co) * Cin + ci0 + ci] = __float2half(s[co][ci * 9 + tap]);
}

__global__ void fold_bn_kernel(
    const float* s0, const float* b0, const float* m0, const float* v0,
    const float* s1, const float* b1, const float* m1, const float* v1,
    const float* s2, const float* b2, const float* m2, const float* v2,
    const float* s3, const float* b3, const float* m3, const float* v3)
{
    const float* S[4] = {s0, s1, s2, s3};
    const float* B[4] = {b0, b1, b2, b3};
    const float* M[4] = {m0, m1, m2, m3};
    const float* V[4] = {v0, v1, v2, v3};
    int set = blockIdx.x;
    int c = threadIdx.x;
    float inv = rsqrtf(V[set][c] + 1e-5f) * S[set][c];
    g_scale[set * 512 + c] = inv;
    g_bias[set * 512 + c]  = B[set][c] - M[set][c] * inv;
}

__global__ void zero_cam_kernel() {
    int t = blockIdx.x * 256 + threadIdx.x;
    *(float4*)&g_cam[t * 4] = make_float4(0.f, 0.f, 0.f, 0.f);
}

// ===========================================================================
// fp16 implicit-GEMM conv 3x3 + BN + ReLU. Tile 128co x 128px (2 rows).
// Grid (4, 32, B), 256 thr. Input fp32 (cvt during staging), weights half
// [tap][co][ci]. OUTH=1: half out; OUTH=0: fp32 out (+optional addend).
// ===========================================================================
#define CONV_AB 10240u                        // one A buf bytes (128*40*2)
#define CONV_SM (2 * CONV_AB + 128 * PMK * 2) // 30720
template <int OUTH>
__global__ __launch_bounds__(256, 2) void conv_f16(
    const float* __restrict__ x, const __half* __restrict__ wT,
    int Cin, int bnset, const float* __restrict__ addend, void* __restrict__ outp)
{
    extern __shared__ char smem[];
    const uint32_t sb = smem_u32(smem);
    __half* Bs = (__half*)(smem + 2 * CONV_AB);

    const int tid = threadIdx.x;
    const int warp = tid >> 5, lane = tid & 31;
    const int wm = (warp & 3) * 32, wn = (warp >> 2) * 64;
    const int coBase = blockIdx.x * 128;
    const int pixBase = blockIdx.y * 128;
    const int y0 = blockIdx.y * 2;
    const int bb = blockIdx.z;
    const float* xb = x + (size_t)bb * Cin * 4096;
    const int NKB = (Cin >> 5) * 9;

    const int p = tid & 127;          // pixel
    const int h = (tid >> 7) * 16;    // ci half-range
    const int yy = p >> 6, xx = p & 63;

    float acc[2][8][4];
#pragma unroll
    for (int i = 0; i < 2; i++)
#pragma unroll
        for (int j = 0; j < 8; j++)
#pragma unroll
            for (int c = 0; c < 4; c++) acc[i][j][c] = 0.f;

    auto stageA = [&](int kb) {
        const int cib = kb / 9, tap = kb - cib * 9;
        const __half* wrow = wT + ((size_t)tap * 512 + coBase) * Cin + (cib << 5);
        const uint32_t dA = sb + (uint32_t)(kb & 1) * CONV_AB;
#pragma unroll
        for (int i = 0; i < 2; i++) {
            int e = i * 256 + tid;
            int m = e >> 2, c = e & 3;
            cp16(dA + (uint32_t)(m * PMK + c * 8) * 2, wrow + (size_t)m * Cin + c * 8);
        }
    };

    stageA(0);
    CP_COMMIT();
    for (int kb = 0; kb < NKB; kb++) {
        if (kb + 1 < NKB) { stageA(kb + 1); CP_COMMIT(); }
        // B: im2col (fp32 LDG -> half STS), single buffer
        {
            const int cib = kb / 9, tap = kb - cib * 9;
            const int dy = tap / 3 - 1, dx = tap - (tap / 3) * 3 - 1;
            const int ys = y0 + yy + dy, xs = xx + dx;
            const bool ok = ((unsigned)ys < 64u) && ((unsigned)xs < 64u);
            const float* base = xb + ((size_t)((cib << 5) + h) << 12) + (ys << 6) + xs;
            float v[16];
#pragma unroll
            for (int j = 0; j < 16; j++) v[j] = ok ? __ldg(base + ((size_t)j << 12)) : 0.f;
            __half2* bd = (__half2*)(Bs + p * PMK + h);
#pragma unroll
            for (int c2 = 0; c2 < 8; c2++) bd[c2] = __floats2half2_rn(v[2 * c2], v[2 * c2 + 1]);
        }
        if (kb + 1 < NKB) CP_WAIT1(); else CP_WAIT0();
        __syncthreads();
        mma_core<0, 0>(sb + (uint32_t)(kb & 1) * CONV_AB, sb + 2 * CONV_AB, wm, wn, lane, acc);
        __syncthreads();
    }

    // epilogue
    const int grp = lane >> 2, tig = lane & 3;
#pragma unroll
    for (int fm = 0; fm < 2; fm++)
#pragma unroll
        for (int hf = 0; hf < 2; hf++) {
            const int co = coBase + wm + fm * 16 + grp + hf * 8;
            const float sc = g_scale[bnset * 512 + co];
            const float bi = g_bias[bnset * 512 + co];
            const size_t rb = (((size_t)(bb * 512 + co)) << 12) + pixBase;
#pragma unroll
            for (int fn = 0; fn < 8; fn++) {
                const int n = wn + fn * 8 + tig * 2;
                float v0 = fmaxf(acc[fm][fn][hf * 2 + 0] * sc + bi, 0.f);
                float v1 = fmaxf(acc[fm][fn][hf * 2 + 1] * sc + bi, 0.f);
                if (OUTH) {
                    *(__half2*)&((__half*)outp)[rb + n] = __floats2half2_rn(v0, v1);
                } else {
                    if (addend) {
                        const float2 a = *(const float2*)&addend[rb + n];
                        v0 += a.x; v1 += a.y;
                    }
                    float2 st = {v0, v1};
                    *(float2*)&((float*)outp)[rb + n] = st;
                }
            }
        }
}

// ===========================================================================
// fp16 GEMM: D[m][n] = sum_k a(m,k) b(n,k).  Tile 128x128, KB=32.
// AL: 0 A global [m][k]; 1 A global [k][m].  BL same for B.
// EP: 0 none | 1 +bias[m] | 2 gamma*acc + half residual | 3 qk split | 4 atomicAdd split-k
// OUTH: 1 half out, 0 fp32 out.
// For EP==4: K is the PER-SPLIT k-length (512); blockIdx.z = bb*8 + split.
// ===========================================================================
template <int AL, int BL, int EP, int OUTH>
__global__ __launch_bounds__(256, 2) void gemm_f16(
    const __half* __restrict__ A, const __half* __restrict__ Bm, void* __restrict__ Cp,
    int lda, int ldb, int ldc, int K,
    long sA, long sB, long sC,
    const __half* __restrict__ A2, const float* __restrict__ bias, const float* __restrict__ bias2,
    const float* __restrict__ gamma, const __half* __restrict__ add, long sAdd,
    __half* __restrict__ C2, long sC2)
{
    extern __shared__ char smem[];
    constexpr uint32_t ASZ = (AL ? 32 * PKM : 128 * PMK) * 2;
    constexpr uint32_t BSZ = (BL ? 32 * PKM : 128 * PMK) * 2;
    const uint32_t sb = smem_u32(smem);
    const uint32_t aB[2] = {sb, sb + ASZ};
    const uint32_t bB[2] = {sb + 2 * ASZ, sb + 2 * ASZ + BSZ};

    const int tid = threadIdx.x;
    const int warp = tid >> 5, lane = tid & 31;
    const int wm = (warp & 3) * 32, wn = (warp >> 2) * 64;
    const int mBase = blockIdx.x * 128;
    const int nBase = blockIdx.y * 128;
    const int bb   = (EP == 4) ? (blockIdx.z >> 3) : blockIdx.z;
    const int kOff = (EP == 4) ? (blockIdx.z & 7) * 512 : 0;

    const __half* Ag = A + (size_t)bb * sA;
    const __half* Bg = Bm + (size_t)bb * sB;
    const int NKB = K >> 5;

    float acc[2][8][4];
#pragma unroll
    for (int i = 0; i < 2; i++)
#pragma unroll
        for (int j = 0; j < 8; j++)
#pragma unroll
            for (int c = 0; c < 4; c++) acc[i][j][c] = 0.f;

    auto stage = [&](int kb) {
        const int k0 = (kb << 5) + kOff;
        const int buf = kb & 1;
        if (AL == 0) {
#pragma unroll
            for (int i = 0; i < 2; i++) {
                int e = i * 256 + tid;
                int m = e >> 2, c = e & 3;
                const __half* src;
                if (EP == 3)
                    src = (m < 64 ? A + (size_t)m * lda : A2 + (size_t)(m - 64) * lda) + k0 + c * 8;
                else
                    src = Ag + (size_t)(mBase + m) * lda + k0 + c * 8;
                cp16(aB[buf] + (uint32_t)(m * PMK + c * 8) * 2, src);
            }
        } else {
#pragma unroll
            for (int i = 0; i < 2; i++) {
                int e = i * 256 + tid;
                int k = e >> 4, c = e & 15;
                cp16(aB[buf] + (uint32_t)(k * PKM + c * 8) * 2,
                     Ag + (size_t)(k0 + k) * lda + mBase + c * 8);
            }
        }
        if (BL == 0) {
#pragma unroll
            for (int i = 0; i < 2; i++) {
                int e = i * 256 + tid;
                int n = e >> 2, c = e & 3;
                cp16(bB[buf] + (uint32_t)(n * PMK + c * 8) * 2,
                     Bg + (size_t)(nBase + n) * ldb + k0 + c * 8);
            }
        } else {
#pragma unroll
            for (int i = 0; i < 2; i++) {
                int e = i * 256 + tid;
                int k = e >> 4, c = e & 15;
                cp16(bB[buf] + (uint32_t)(k * PKM + c * 8) * 2,
                     Bg + (size_t)(k0 + k) * ldb + nBase + c * 8);
            }
        }
    };

    stage(0);
    CP_COMMIT();
    for (int kb = 0; kb < NKB; kb++) {
        if (kb + 1 < NKB) { stage(kb + 1); CP_COMMIT(); CP_WAIT1(); } else CP_WAIT0();
        __syncthreads();
        mma_core<AL, BL>(aB[kb & 1], bB[kb & 1], wm, wn, lane, acc);
        __syncthreads();
    }

    // epilogue
    const int grp = lane >> 2, tig = lane & 3;
    const float gv = (EP == 2) ? __ldg(&gamma[0]) : 0.f;
#pragma unroll
    for (int fm = 0; fm < 2; fm++)
#pragma unroll
        for (int hf = 0; hf < 2; hf++) {
            const int m = mBase + wm + fm * 16 + grp + hf * 8;
            float bv = 0.f;
            if (EP == 1) bv = __ldg(&bias[m]);
            if (EP == 3) bv = (m < 64) ? __ldg(&bias[m]) : __ldg(&bias2[m - 64]);
            __half* hdst = nullptr;
            float* fdst = nullptr;
            if (EP == 3)
                hdst = (m < 64) ? (__half*)Cp + (size_t)bb * sC + (size_t)m * ldc
                                : C2 + (size_t)bb * sC2 + (size_t)(m - 64) * ldc;
            else if (OUTH) hdst = (__half*)Cp + (size_t)bb * sC + (size_t)m * ldc;
            else           fdst = (float*)Cp + (size_t)bb * sC + (size_t)m * ldc;
            const __half* ap = (EP == 2) ? add + (size_t)bb * sAdd + (size_t)m * ldc : nullptr;
#pragma unroll
            for (int fn = 0; fn < 8; fn++) {
                const int n = nBase + wn + fn * 8 + tig * 2;
                float v0 = acc[fm][fn][hf * 2 + 0];
                float v1 = acc[fm][fn][hf * 2 + 1];
                if (EP == 1 || EP == 3) { v0 += bv; v1 += bv; }
                if (EP == 2) {
                    const float2 r = __half22float2(*(const __half2*)&ap[n]);
                    v0 = gv * v0 + r.x; v1 = gv * v1 + r.y;
                }
                if (EP == 4) {
                    atomicAdd(&fdst[n], v0);
                    atomicAdd(&fdst[n + 1], v1);
                } else if (hdst) {
                    *(__half2*)&hdst[n] = __floats2half2_rn(v0, v1);
                } else {
                    float2 st = {v0, v1};
                    *(float2*)&fdst[n] = st;
                }
            }
        }
}

// ===========================================================================
// Softmaxes: read fp32 logits, write fp16 attn (separate buffers)
// ===========================================================================
__global__ void softmax4096_kernel(const float* __restrict__ e, __half* __restrict__ o)
{
    const float* p = e + (size_t)blockIdx.x * 4096;
    __half* po = o + (size_t)blockIdx.x * 4096;
    const int tid = threadIdx.x;
    float4 v[4];
    float mx = -1e30f;
#pragma unroll
    for (int i = 0; i < 4; i++) {
        v[i] = *(const float4*)&p[i * 1024 + tid * 4];
        mx = fmaxf(mx, fmaxf(fmaxf(v[i].x, v[i].y), fmaxf(v[i].z, v[i].w)));
    }
    __shared__ float red[8];
#pragma unroll
    for (int off = 16; off; off >>= 1) mx = fmaxf(mx, __shfl_xor_sync(0xffffffffu, mx, off));
    if ((tid & 31) == 0) red[tid >> 5] = mx;
    __syncthreads();
    mx = red[0];
#pragma unroll
    for (int i = 1; i < 8; i++) mx = fmaxf(mx, red[i]);
    __syncthreads();
    float s = 0.f;
#pragma unroll
    for (int i = 0; i < 4; i++) {
        v[i].x = __expf(v[i].x - mx); v[i].y = __expf(v[i].y - mx);
        v[i].z = __expf(v[i].z - mx); v[i].w = __expf(v[i].w - mx);
        s += v[i].x + v[i].y + v[i].z + v[i].w;
    }
#pragma unroll
    for (int off = 16; off; off >>= 1) s += __shfl_xor_sync(0xffffffffu, s, off);
    if ((tid & 31) == 0) red[tid >> 5] = s;
    __syncthreads();
    s = 0.f;
#pragma unroll
    for (int i = 0; i < 8; i++) s += red[i];
    const float inv = 1.f / s;
#pragma unroll
    for (int i = 0; i < 4; i++) {
        __half2* d = (__half2*)&po[i * 1024 + tid * 4];
        d[0] = __floats2half2_rn(v[i].x * inv, v[i].y * inv);
        d[1] = __floats2half2_rn(v[i].z * inv, v[i].w * inv);
    }
}

__global__ void softmax512_cam_kernel(const float* __restrict__ e, __half* __restrict__ o)
{
    const float* p = e + (size_t)blockIdx.x * 512;
    __half* po = o + (size_t)blockIdx.x * 512;
    const int tid = threadIdx.x;
    float4 v = *(const float4*)&p[tid * 4];
    float mn = fminf(fminf(v.x, v.y), fminf(v.z, v.w));
    __shared__ float red[4];
#pragma unroll
    for (int off = 16; off; off >>= 1) mn = fminf(mn, __shfl_xor_sync(0xffffffffu, mn, off));
    if ((tid & 31) == 0) red[tid >> 5] = mn;
    __syncthreads();
    mn = fminf(fminf(red[0], red[1]), fminf(red[2], red[3]));
    __syncthreads();
    v.x = __expf(mn - v.x); v.y = __expf(mn - v.y);
    v.z = __expf(mn - v.z); v.w = __expf(mn - v.w);
    float s = v.x + v.y + v.z + v.w;
#pragma unroll
    for (int off = 16; off; off >>= 1) s += __shfl_xor_sync(0xffffffffu, s, off);
    if ((tid & 31) == 0) red[tid >> 5] = s;
    __syncthreads();
    s = red[0] + red[1] + red[2] + red[3];
    const float inv = 1.f / s;
    __half2* d = (__half2*)&po[tid * 4];
    d[0] = __floats2half2_rn(v.x * inv, v.y * inv);
    d[1] = __floats2half2_rn(v.z * inv, v.w * inv);
}

// ===========================================================================
// Launch
// ===========================================================================
static inline int smg(int al, int bl) {
    int a = (al ? 32 * PKM : 128 * PMK) * 2;
    int b = (bl ? 32 * PKM : 128 * PMK) * 2;
    return 2 * a + 2 * b;
}

extern "C" void kernel_launch(void* const* d_in, const int* in_sizes, int n_in,
                              void* d_out, int out_size)
{
    (void)in_sizes; (void)n_in; (void)out_size;
    const float* x   = (const float*)d_in[0];
    const float* w5a = (const float*)d_in[1];
    const float* w5c = (const float*)d_in[6];
    const float* wq  = (const float*)d_in[11];
    const float* bq  = (const float*)d_in[12];
    const float* wk  = (const float*)d_in[13];
    const float* bk  = (const float*)d_in[14];
    const float* wv  = (const float*)d_in[15];
    const float* bv  = (const float*)d_in[16];
    const float* gpam = (const float*)d_in[17];
    const float* gcam = (const float*)d_in[18];
    const float* w51 = (const float*)d_in[19];
    const float* w52 = (const float*)d_in[24];
    float* out = (float*)d_out;

    __half *f1h, *f2h, *qh, *kh, *vh, *attnh, *camh, *wa, *wc, *w1, *w2, *wqh, *wkh, *wvh;
    float *energy, *cam, *saf, *scf, *sacv;
    cudaGetSymbolAddress((void**)&f1h, g_feat1h);
    cudaGetSymbolAddress((void**)&f2h, g_feat2h);
    cudaGetSymbolAddress((void**)&qh, g_qh);
    cudaGetSymbolAddress((void**)&kh, g_kh);
    cudaGetSymbolAddress((void**)&vh, g_vh);
    cudaGetSymbolAddress((void**)&attnh, g_attnh);
    cudaGetSymbolAddress((void**)&camh, g_camh);
    cudaGetSymbolAddress((void**)&energy, g_energy);
    cudaGetSymbolAddress((void**)&cam, g_cam);
    cudaGetSymbolAddress((void**)&saf, g_saf);
    cudaGetSymbolAddress((void**)&scf, g_scf);
    cudaGetSymbolAddress((void**)&sacv, g_sacv);
    cudaGetSymbolAddress((void**)&wa, g_wa);
    cudaGetSymbolAddress((void**)&wc, g_wc);
    cudaGetSymbolAddress((void**)&w1, g_w1);
    cudaGetSymbolAddress((void**)&w2, g_w2);
    cudaGetSymbolAddress((void**)&wqh, g_wqh);
    cudaGetSymbolAddress((void**)&wkh, g_wkh);
    cudaGetSymbolAddress((void**)&wvh, g_wvh);

    cudaFuncSetAttribute(conv_f16<1>, cudaFuncAttributeMaxDynamicSharedMemorySize, CONV_SM);
    cudaFuncSetAttribute(conv_f16<0>, cudaFuncAttributeMaxDynamicSharedMemorySize, CONV_SM);
    cudaFuncSetAttribute(gemm_f16<0,1,3,1>, cudaFuncAttributeMaxDynamicSharedMemorySize, smg(0,1));
    cudaFuncSetAttribute(gemm_f16<0,1,1,1>, cudaFuncAttributeMaxDynamicSharedMemorySize, smg(0,1));
    cudaFuncSetAttribute(gemm_f16<1,1,0,0>, cudaFuncAttributeMaxDynamicSharedMemorySize, smg(1,1));
    cudaFuncSetAttribute(gemm_f16<0,0,2,0>, cudaFuncAttributeMaxDynamicSharedMemorySize, smg(0,0));
    cudaFuncSetAttribute(gemm_f16<0,0,4,0>, cudaFuncAttributeMaxDynamicSharedMemorySize, smg(0,0));
    cudaFuncSetAttribute(gemm_f16<0,1,2,0>, cudaFuncAttributeMaxDynamicSharedMemorySize, smg(0,1));

    // prep
    f2h_kernel<<<128, 256>>>(wq, wqh, 64 * 512);
    f2h_kernel<<<128, 256>>>(wk, wkh, 64 * 512);
    f2h_kernel<<<1024, 256>>>(wv, wvh, 512 * 512);
    repack_wh<<<dim3(16, 256), 256>>>(w5a, wa, 2048);
    repack_wh<<<dim3(16, 256), 256>>>(w5c, wc, 2048);
    repack_wh<<<dim3(16, 64), 256>>>(w51, w1, 512);
    repack_wh<<<dim3(16, 64), 256>>>(w52, w2, 512);
    fold_bn_kernel<<<4, 512>>>(
        (const float*)d_in[2],  (const float*)d_in[3],  (const float*)d_in[4],  (const float*)d_in[5],
        (const float*)d_in[7],  (const float*)d_in[8],  (const float*)d_in[9],  (const float*)d_in[10],
        (const float*)d_in[20], (const float*)d_in[21], (const float*)d_in[22], (const float*)d_in[23],
        (const float*)d_in[25], (const float*)d_in[26], (const float*)d_in[27], (const float*)d_in[28]);
    zero_cam_kernel<<<512, 256>>>();

    const dim3 cg(4, 32, 2);
    const long F = 512L * 4096, Q = 64L * 4096, E = 4096L * 4096;

    // convs 1/2 -> half feats
    conv_f16<1><<<cg, 256, CONV_SM>>>(x, wa, 2048, 0, nullptr, f1h);
    conv_f16<1><<<cg, 256, CONV_SM>>>(x, wc, 2048, 1, nullptr, f2h);

    // q,k stacked; v
    gemm_f16<0,1,3,1><<<dim3(1, 32, 2), 256, smg(0,1)>>>(
        wqh, f1h, qh, 512, 4096, 4096, 512, 0, F, Q, wkh, bq, bk, nullptr, nullptr, 0, kh, Q);
    gemm_f16<0,1,1,1><<<dim3(4, 32, 2), 256, smg(0,1)>>>(
        wvh, f1h, vh, 512, 4096, 4096, 512, 0, F, F, nullptr, bv, nullptr, nullptr, nullptr, 0, nullptr, 0);

    // PAM energy (fp32 out), softmax -> half attn
    gemm_f16<1,1,0,0><<<dim3(32, 32, 2), 256, smg(1,1)>>>(
        qh, kh, energy, 4096, 4096, 4096, 64, Q, Q, E, nullptr, nullptr, nullptr, nullptr, nullptr, 0, nullptr, 0);
    softmax4096_kernel<<<8192, 256>>>(energy, attnh);

    // sa_feat = gamma*(v@attn^T) + feat1  (fp32 out for conv input)
    gemm_f16<0,0,2,0><<<dim3(4, 32, 2), 256, smg(0,0)>>>(
        vh, attnh, saf, 4096, 4096, 4096, 4096, F, E, F, nullptr, nullptr, nullptr, gpam, f1h, F, nullptr, 0);

    // CAM energy split-K=8 (atomic fp32): K=512 PER SPLIT (fix for R11 bug)
    gemm_f16<0,0,4,0><<<dim3(4, 4, 16), 256, smg(0,0)>>>(
        f2h, f2h, cam, 4096, 4096, 512, 512, F, F, 512L * 512, nullptr, nullptr, nullptr, nullptr, nullptr, 0, nullptr, 0);
    softmax512_cam_kernel<<<1024, 128>>>(cam, camh);

    // sc_feat = gamma*(attn@feat2) + feat2 (fp32 out)
    gemm_f16<0,1,2,0><<<dim3(4, 32, 2), 256, smg(0,1)>>>(
        camh, f2h, scf, 512, 4096, 4096, 512, 512L * 512, F, F, nullptr, nullptr, nullptr, gcam, f2h, F, nullptr, 0);

    // convs 3/4 (fp32 out)
    conv_f16<0><<<cg, 256, CONV_SM>>>(saf, w1, 512, 2, nullptr, sacv);
    conv_f16<0><<<cg, 256, CONV_SM>>>(scf, w2, 512, 3, sacv, out);
}

// round 14
// speedup vs baseline: 2.1095x; 1.0306x over previous
#include <cuda_runtime.h>
#include <cuda_fp16.h>
#include <cstdint>
#include <math.h>

// ===========================================================================
// Globals
// ===========================================================================
__device__ __half g_xr[2 * 4096 * 2048];        // pixel-major half input
__device__ __half g_feat1h[2 * 512 * 4096];
__device__ __half g_feat2h[2 * 512 * 4096];
__device__ __half g_qh[2 * 64 * 4096];
__device__ __half g_kh[2 * 64 * 4096];
__device__ __half g_vh[2 * 512 * 4096];
__device__ __half g_attnh[2 * 4096 * 4096];
__device__ __half g_camh[2 * 512 * 512];
__device__ float  g_energy[2 * 4096 * 4096];
__device__ float  g_cam[2 * 512 * 512];
__device__ float  g_saf[2 * 512 * 4096];
__device__ float  g_scf[2 * 512 * 4096];
__device__ float  g_sacv[2 * 512 * 4096];
__device__ float  g_scale[4 * 512];
__device__ float  g_bias[4 * 512];
__device__ __half g_wa[9 * 512 * 2048];
__device__ __half g_wc[9 * 512 * 2048];
__device__ __half g_w1[9 * 512 * 512];
__device__ __half g_w2[9 * 512 * 512];
__device__ __half g_wqh[64 * 512];
__device__ __half g_wkh[64 * 512];
__device__ __half g_wvh[512 * 512];

// ===========================================================================
// Helpers
// ===========================================================================
__device__ __forceinline__ uint32_t smem_u32(const void* p) {
    uint32_t a;
    asm("{ .reg .u64 t; cvta.to.shared.u64 t, %1; cvt.u32.u64 %0, t; }" : "=r"(a) : "l"(p));
    return a;
}
__device__ __forceinline__ void cp16(uint32_t dst, const void* src) {
    asm volatile("cp.async.ca.shared.global [%0], [%1], 16;" :: "r"(dst), "l"(src));
}
__device__ __forceinline__ void cp16z(uint32_t dst, const void* src, int sz) {
    asm volatile("cp.async.ca.shared.global [%0], [%1], 16, %2;" :: "r"(dst), "l"(src), "r"(sz));
}
#define CP_COMMIT() asm volatile("cp.async.commit_group;" ::: "memory")
#define CP_WAIT0()  asm volatile("cp.async.wait_group 0;" ::: "memory")
#define CP_WAIT1()  asm volatile("cp.async.wait_group 1;" ::: "memory")

#define LDSM_X4(r, a) \
    asm volatile("ldmatrix.sync.aligned.m8n8.x4.shared.b16 {%0,%1,%2,%3}, [%4];" \
        : "=r"((r)[0]), "=r"((r)[1]), "=r"((r)[2]), "=r"((r)[3]) : "r"(a))
#define LDSM_X4T(r, a) \
    asm volatile("ldmatrix.sync.aligned.m8n8.x4.trans.shared.b16 {%0,%1,%2,%3}, [%4];" \
        : "=r"((r)[0]), "=r"((r)[1]), "=r"((r)[2]), "=r"((r)[3]) : "r"(a))
#define MMA_F16(c, a, b0_, b1_) \
    asm volatile("mma.sync.aligned.m16n8k16.row.col.f32.f16.f16.f32 " \
        "{%0,%1,%2,%3},{%4,%5,%6,%7},{%8,%9},{%0,%1,%2,%3};" \
        : "+f"((c)[0]), "+f"((c)[1]), "+f"((c)[2]), "+f"((c)[3]) \
        : "r"((a)[0]), "r"((a)[1]), "r"((a)[2]), "r"((a)[3]), "r"(b0_), "r"(b1_))

#define PMK 40
#define PKM 136

// ===========================================================================
// fp16 MMA core: tile 128m x 128n, KB=32. 8 warps = 4m x 2n, warp 32x64.
// ===========================================================================
template <int AL, int BL>
__device__ __forceinline__ void mma_core(
    uint32_t aB, uint32_t bB, int wm, int wn, int lane, float (&acc)[2][8][4])
{
    const int w = lane & 7, q = lane >> 3;
#pragma unroll
    for (int s = 0; s < 2; s++) {
        const int k16 = s * 16;
        uint32_t A[2][4];
#pragma unroll
        for (int fm = 0; fm < 2; fm++) {
            const int m0 = wm + fm * 16;
            if (AL == 0) {
                LDSM_X4(A[fm], aB + (uint32_t)((m0 + (lane & 15)) * PMK + k16 + (lane >> 4) * 8) * 2);
            } else {
                LDSM_X4T(A[fm], aB + (uint32_t)((k16 + (q >> 1) * 8 + w) * PKM + m0 + (q & 1) * 8) * 2);
            }
        }
        uint32_t B[8][2];
#pragma unroll
        for (int g = 0; g < 4; g++) {
            uint32_t r[4];
            const int n0 = wn + g * 16;
            if (BL == 0) {
                LDSM_X4(r, bB + (uint32_t)((n0 + (q >> 1) * 8 + w) * PMK + k16 + (q & 1) * 8) * 2);
            } else {
                LDSM_X4T(r, bB + (uint32_t)((k16 + (q & 1) * 8 + w) * PKM + n0 + (q >> 1) * 8) * 2);
            }
            B[g * 2][0] = r[0]; B[g * 2][1] = r[1];
            B[g * 2 + 1][0] = r[2]; B[g * 2 + 1][1] = r[3];
        }
#pragma unroll
        for (int fm = 0; fm < 2; fm++)
#pragma unroll
            for (int fn = 0; fn < 8; fn++)
                MMA_F16(acc[fm][fn], A[fm], B[fn][0], B[fn][1]);
    }
}

// ===========================================================================
// Prep kernels
// ===========================================================================
__global__ void f2h_kernel(const float* __restrict__ in, __half* __restrict__ o, int n) {
    int t = blockIdx.x * 256 + threadIdx.x;
    if (t < n) o[t] = __float2half(in[t]);
}

// x[bb][ci][px] f32 -> xr[bb][px][ci] half. Tile 32ci x 32px. Grid (64, 128, 2).
__global__ void transpose_x(const float* __restrict__ x, __half* __restrict__ xr) {
    __shared__ __half s[32][34];
    const int tid = threadIdx.x;
    const int ci0 = blockIdx.x * 32;
    const int px0 = blockIdx.y * 32;
    const int bb = blockIdx.z;
    const float* xb = x + ((size_t)bb * 2048 + ci0) * 4096 + px0;
#pragma unroll
    for (int i = 0; i < 4; i++) {
        int e = i * 256 + tid;
        int r = e >> 5, c = e & 31;
        s[r][c] = __float2half(xb[(size_t)r * 4096 + c]);
    }
    __syncthreads();
    __half* ob = g_xr + ((size_t)bb * 4096 + px0) * 2048 + ci0;
#pragma unroll
    for (int i = 0; i < 4; i++) {
        int e = i * 256 + tid;
        int p = e >> 5, c = e & 31;
        ob[(size_t)p * 2048 + c] = s[c][p];
    }
    (void)xr;
}

// repack w[co][ci][tap] (f32) -> o[tap][co][ci] (half). Grid (16, Cin/8), 256 thr.
__global__ void repack_wh(const float* __restrict__ w, __half* __restrict__ o, int Cin) {
    __shared__ float s[32][73];
    const int tid = threadIdx.x;
    const int co0 = blockIdx.x * 32;
    const int ci0 = blockIdx.y * 8;
#pragma unroll
    for (int i = 0; i < 9; i++) {
        int e = i * 256 + tid;
        int co = e / 72, r = e % 72;
        s[co][r] = w[((size_t)(co0 + co) * Cin + ci0 + r / 9) * 9 + (r % 9)];
    }
    __syncthreads();
    const int ci = tid & 7, co = tid >> 3;
#pragma unroll
    for (int tap = 0; tap < 9; tap++)
        o[((size_t)tap * 512 + co0 + co) * Cin + ci0 + ci] = __float2half(s[co][ci * 9 + tap]);
}

__global__ void fold_bn_kernel(
    const float* s0, const float* b0, const float* m0, const float* v0,
    const float* s1, const float* b1, const float* m1, const float* v1,
    const float* s2, const float* b2, const float* m2, const float* v2,
    const float* s3, const float* b3, const float* m3, const float* v3)
{
    const float* S[4] = {s0, s1, s2, s3};
    const float* B[4] = {b0, b1, b2, b3};
    const float* M[4] = {m0, m1, m2, m3};
    const float* V[4] = {v0, v1, v2, v3};
    int set = blockIdx.x;
    int c = threadIdx.x;
    float inv = rsqrtf(V[set][c] + 1e-5f) * S[set][c];
    g_scale[set * 512 + c] = inv;
    g_bias[set * 512 + c]  = B[set][c] - M[set][c] * inv;
}

__global__ void zero_cam_kernel() {
    int t = blockIdx.x * 256 + threadIdx.x;
    *(float4*)&g_cam[t * 4] = make_float4(0.f, 0.f, 0.f, 0.f);
}

// ===========================================================================
// Fast conv for pixel-major half input (big convs). Tile 128co x 128px.
// Grid (4, 32, B), 256 thr. A+B both cp.async double-buffered. Half out.
// ===========================================================================
#define CAB 10240u                 // one buf bytes (128*40*2)
#define CPX_SM (4 * CAB)           // 40960
__global__ __launch_bounds__(256, 2) void conv_px(
    const __half* __restrict__ xr, const __half* __restrict__ wT,
    int Cin, int bnset, __half* __restrict__ outp)
{
    extern __shared__ char smem[];
    const uint32_t sb = smem_u32(smem);
    const uint32_t aB[2] = {sb, sb + CAB};
    const uint32_t bB[2] = {sb + 2 * CAB, sb + 3 * CAB};

    const int tid = threadIdx.x;
    const int warp = tid >> 5, lane = tid & 31;
    const int wm = (warp & 3) * 32, wn = (warp >> 2) * 64;
    const int coBase = blockIdx.x * 128;
    const int pixBase = blockIdx.y * 128;
    const int y0 = blockIdx.y * 2;
    const int bb = blockIdx.z;
    const __half* xb = xr + (size_t)bb * 4096 * 2048;
    const int NKB = (Cin >> 5) * 9;

    const int n = tid >> 1;                 // B row (pixel in tile), 2 chunks/thread
    const int c2 = (tid & 1) * 2;           // chunk pair base
    const int yy = n >> 6, xx = n & 63;

    float acc[2][8][4];
#pragma unroll
    for (int i = 0; i < 2; i++)
#pragma unroll
        for (int j = 0; j < 8; j++)
#pragma unroll
            for (int c = 0; c < 4; c++) acc[i][j][c] = 0.f;

    auto stage = [&](int kb) {
        const int cib = kb / 9, tap = kb - cib * 9;
        const int ci0 = cib << 5;
        const int buf = kb & 1;
        // A: weights [co][ci] contiguous
        const __half* wrow = wT + ((size_t)tap * 512 + coBase) * Cin + ci0;
#pragma unroll
        for (int i = 0; i < 2; i++) {
            int e = i * 256 + tid;
            int m = e >> 2, c = e & 3;
            cp16(aB[buf] + (uint32_t)(m * PMK + c * 8) * 2, wrow + (size_t)m * Cin + c * 8);
        }
        // B: pixel-major gather, 16B aligned regardless of tap
        const int dy = tap / 3 - 1, dx = tap - (tap / 3) * 3 - 1;
        const int ys = y0 + yy + dy, xs = xx + dx;
        const int ok = (((unsigned)ys < 64u) && ((unsigned)xs < 64u)) ? 16 : 0;
        const __half* src = xb + ((size_t)((ys << 6) + xs) * 2048) + ci0 + c2 * 8;
        cp16z(bB[buf] + (uint32_t)(n * PMK + c2 * 8) * 2, ok ? src : xb, ok);
        cp16z(bB[buf] + (uint32_t)(n * PMK + (c2 + 1) * 8) * 2, ok ? (src + 8) : xb, ok);
    };

    stage(0);
    CP_COMMIT();
    for (int kb = 0; kb < NKB; kb++) {
        if (kb + 1 < NKB) { stage(kb + 1); CP_COMMIT(); CP_WAIT1(); } else CP_WAIT0();
        __syncthreads();
        mma_core<0, 0>(aB[kb & 1], bB[kb & 1], wm, wn, lane, acc);
        __syncthreads();
    }

    const int grp = lane >> 2, tig = lane & 3;
#pragma unroll
    for (int fm = 0; fm < 2; fm++)
#pragma unroll
        for (int hf = 0; hf < 2; hf++) {
            const int co = coBase + wm + fm * 16 + grp + hf * 8;
            const float sc = g_scale[bnset * 512 + co];
            const float bi = g_bias[bnset * 512 + co];
            const size_t rb = (((size_t)(bb * 512 + co)) << 12) + pixBase;
#pragma unroll
            for (int fn = 0; fn < 8; fn++) {
                const int nn = wn + fn * 8 + tig * 2;
                float v0 = fmaxf(acc[fm][fn][hf * 2 + 0] * sc + bi, 0.f);
                float v1 = fmaxf(acc[fm][fn][hf * 2 + 1] * sc + bi, 0.f);
                *(__half2*)&outp[rb + nn] = __floats2half2_rn(v0, v1);
            }
        }
}

// ===========================================================================
// Gather conv (small convs, fp32 input [c][px], fp32 out + optional addend)
// ===========================================================================
#define CONV_SM (2 * CAB + 128 * PMK * 2)
__global__ __launch_bounds__(256, 2) void conv_f16(
    const float* __restrict__ x, const __half* __restrict__ wT,
    int Cin, int bnset, const float* __restrict__ addend, float* __restrict__ outp)
{
    extern __shared__ char smem[];
    const uint32_t sb = smem_u32(smem);
    __half* Bs = (__half*)(smem + 2 * CAB);

    const int tid = threadIdx.x;
    const int warp = tid >> 5, lane = tid & 31;
    const int wm = (warp & 3) * 32, wn = (warp >> 2) * 64;
    const int coBase = blockIdx.x * 128;
    const int pixBase = blockIdx.y * 128;
    const int y0 = blockIdx.y * 2;
    const int bb = blockIdx.z;
    const float* xb = x + (size_t)bb * Cin * 4096;
    const int NKB = (Cin >> 5) * 9;

    const int p = tid & 127;
    const int h = (tid >> 7) * 16;
    const int yy = p >> 6, xx = p & 63;

    float acc[2][8][4];
#pragma unroll
    for (int i = 0; i < 2; i++)
#pragma unroll
        for (int j = 0; j < 8; j++)
#pragma unroll
            for (int c = 0; c < 4; c++) acc[i][j][c] = 0.f;

    auto stageA = [&](int kb) {
        const int cib = kb / 9, tap = kb - cib * 9;
        const __half* wrow = wT + ((size_t)tap * 512 + coBase) * Cin + (cib << 5);
        const uint32_t dA = sb + (uint32_t)(kb & 1) * CAB;
#pragma unroll
        for (int i = 0; i < 2; i++) {
            int e = i * 256 + tid;
            int m = e >> 2, c = e & 3;
            cp16(dA + (uint32_t)(m * PMK + c * 8) * 2, wrow + (size_t)m * Cin + c * 8);
        }
    };

    stageA(0);
    CP_COMMIT();
    for (int kb = 0; kb < NKB; kb++) {
        if (kb + 1 < NKB) { stageA(kb + 1); CP_COMMIT(); }
        {
            const int cib = kb / 9, tap = kb - cib * 9;
            const int dy = tap / 3 - 1, dx = tap - (tap / 3) * 3 - 1;
            const int ys = y0 + yy + dy, xs = xx + dx;
            const bool ok = ((unsigned)ys < 64u) && ((unsigned)xs < 64u);
            const float* base = xb + ((size_t)((cib << 5) + h) << 12) + (ys << 6) + xs;
            float v[16];
#pragma unroll
            for (int j = 0; j < 16; j++) v[j] = ok ? __ldg(base + ((size_t)j << 12)) : 0.f;
            __half2* bd = (__half2*)(Bs + p * PMK + h);
#pragma unroll
            for (int c2 = 0; c2 < 8; c2++) bd[c2] = __floats2half2_rn(v[2 * c2], v[2 * c2 + 1]);
        }
        if (kb + 1 < NKB) CP_WAIT1(); else CP_WAIT0();
        __syncthreads();
        mma_core<0, 0>(sb + (uint32_t)(kb & 1) * CAB, sb + 2 * CAB, wm, wn, lane, acc);
        __syncthreads();
    }

    const int grp = lane >> 2, tig = lane & 3;
#pragma unroll
    for (int fm = 0; fm < 2; fm++)
#pragma unroll
        for (int hf = 0; hf < 2; hf++) {
            const int co = coBase + wm + fm * 16 + grp + hf * 8;
            const float sc = g_scale[bnset * 512 + co];
            const float bi = g_bias[bnset * 512 + co];
            const size_t rb = (((size_t)(bb * 512 + co)) << 12) + pixBase;
#pragma unroll
            for (int fn = 0; fn < 8; fn++) {
                const int n = wn + fn * 8 + tig * 2;
                float v0 = fmaxf(acc[fm][fn][hf * 2 + 0] * sc + bi, 0.f);
                float v1 = fmaxf(acc[fm][fn][hf * 2 + 1] * sc + bi, 0.f);
                if (addend) {
                    const float2 a = *(const float2*)&addend[rb + n];
                    v0 += a.x; v1 += a.y;
                }
                float2 st = {v0, v1};
                *(float2*)&outp[rb + n] = st;
            }
        }
}

// ===========================================================================
// fp16 GEMM (unchanged from R12)
// ===========================================================================
template <int AL, int BL, int EP, int OUTH>
__global__ __launch_bounds__(256, 2) void gemm_f16(
    const __half* __restrict__ A, const __half* __restrict__ Bm, void* __restrict__ Cp,
    int lda, int ldb, int ldc, int K,
    long sA, long sB, long sC,
    const __half* __restrict__ A2, const float* __restrict__ bias, const float* __restrict__ bias2,
    const float* __restrict__ gamma, const __half* __restrict__ add, long sAdd,
    __half* __restrict__ C2, long sC2)
{
    extern __shared__ char smem[];
    constexpr uint32_t ASZ = (AL ? 32 * PKM : 128 * PMK) * 2;
    constexpr uint32_t BSZ = (BL ? 32 * PKM : 128 * PMK) * 2;
    const uint32_t sb = smem_u32(smem);
    const uint32_t aB[2] = {sb, sb + ASZ};
    const uint32_t bB[2] = {sb + 2 * ASZ, sb + 2 * ASZ + BSZ};

    const int tid = threadIdx.x;
    const int warp = tid >> 5, lane = tid & 31;
    const int wm = (warp & 3) * 32, wn = (warp >> 2) * 64;
    const int mBase = blockIdx.x * 128;
    const int nBase = blockIdx.y * 128;
    const int bb   = (EP == 4) ? (blockIdx.z >> 3) : blockIdx.z;
    const int kOff = (EP == 4) ? (blockIdx.z & 7) * 512 : 0;

    const __half* Ag = A + (size_t)bb * sA;
    const __half* Bg = Bm + (size_t)bb * sB;
    const int NKB = K >> 5;

    float acc[2][8][4];
#pragma unroll
    for (int i = 0; i < 2; i++)
#pragma unroll
        for (int j = 0; j < 8; j++)
#pragma unroll
            for (int c = 0; c < 4; c++) acc[i][j][c] = 0.f;

    auto stage = [&](int kb) {
        const int k0 = (kb << 5) + kOff;
        const int buf = kb & 1;
        if (AL == 0) {
#pragma unroll
            for (int i = 0; i < 2; i++) {
                int e = i * 256 + tid;
                int m = e >> 2, c = e & 3;
                const __half* src;
                if (EP == 3)
                    src = (m < 64 ? A + (size_t)m * lda : A2 + (size_t)(m - 64) * lda) + k0 + c * 8;
                else
                    src = Ag + (size_t)(mBase + m) * lda + k0 + c * 8;
                cp16(aB[buf] + (uint32_t)(m * PMK + c * 8) * 2, src);
            }
        } else {
#pragma unroll
            for (int i = 0; i < 2; i++) {
                int e = i * 256 + tid;
                int k = e >> 4, c = e & 15;
                cp16(aB[buf] + (uint32_t)(k * PKM + c * 8) * 2,
                     Ag + (size_t)(k0 + k) * lda + mBase + c * 8);
            }
        }
        if (BL == 0) {
#pragma unroll
            for (int i = 0; i < 2; i++) {
                int e = i * 256 + tid;
                int n = e >> 2, c = e & 3;
                cp16(bB[buf] + (uint32_t)(n * PMK + c * 8) * 2,
                     Bg + (size_t)(nBase + n) * ldb + k0 + c * 8);
            }
        } else {
#pragma unroll
            for (int i = 0; i < 2; i++) {
                int e = i * 256 + tid;
                int k = e >> 4, c = e & 15;
                cp16(bB[buf] + (uint32_t)(k * PKM + c * 8) * 2,
                     Bg + (size_t)(k0 + k) * ldb + nBase + c * 8);
            }
        }
    };

    stage(0);
    CP_COMMIT();
    for (int kb = 0; kb < NKB; kb++) {
        if (kb + 1 < NKB) { stage(kb + 1); CP_COMMIT(); CP_WAIT1(); } else CP_WAIT0();
        __syncthreads();
        mma_core<AL, BL>(aB[kb & 1], bB[kb & 1], wm, wn, lane, acc);
        __syncthreads();
    }

    const int grp = lane >> 2, tig = lane & 3;
    const float gv = (EP == 2) ? __ldg(&gamma[0]) : 0.f;
#pragma unroll
    for (int fm = 0; fm < 2; fm++)
#pragma unroll
        for (int hf = 0; hf < 2; hf++) {
            const int m = mBase + wm + fm * 16 + grp + hf * 8;
            float bv = 0.f;
            if (EP == 1) bv = __ldg(&bias[m]);
            if (EP == 3) bv = (m < 64) ? __ldg(&bias[m]) : __ldg(&bias2[m - 64]);
            __half* hdst = nullptr;
            float* fdst = nullptr;
            if (EP == 3)
                hdst = (m < 64) ? (__half*)Cp + (size_t)bb * sC + (size_t)m * ldc
                                : C2 + (size_t)bb * sC2 + (size_t)(m - 64) * ldc;
            else if (OUTH) hdst = (__half*)Cp + (size_t)bb * sC + (size_t)m * ldc;
            else           fdst = (float*)Cp + (size_t)bb * sC + (size_t)m * ldc;
            const __half* ap = (EP == 2) ? add + (size_t)bb * sAdd + (size_t)m * ldc : nullptr;
#pragma unroll
            for (int fn = 0; fn < 8; fn++) {
                const int n = nBase + wn + fn * 8 + tig * 2;
                float v0 = acc[fm][fn][hf * 2 + 0];
                float v1 = acc[fm][fn][hf * 2 + 1];
                if (EP == 1 || EP == 3) { v0 += bv; v1 += bv; }
                if (EP == 2) {
                    const float2 r = __half22float2(*(const __half2*)&ap[n]);
                    v0 = gv * v0 + r.x; v1 = gv * v1 + r.y;
                }
                if (EP == 4) {
                    atomicAdd(&fdst[n], v0);
                    atomicAdd(&fdst[n + 1], v1);
                } else if (hdst) {
                    *(__half2*)&hdst[n] = __floats2half2_rn(v0, v1);
                } else {
                    float2 st = {v0, v1};
                    *(float2*)&fdst[n] = st;
                }
            }
        }
}

// ===========================================================================
// Softmaxes
// ===========================================================================
__global__ void softmax4096_kernel(const float* __restrict__ e, __half* __restrict__ o)
{
    const float* p = e + (size_t)blockIdx.x * 4096;
    __half* po = o + (size_t)blockIdx.x * 4096;
    const int tid = threadIdx.x;
    float4 v[4];
    float mx = -1e30f;
#pragma unroll
    for (int i = 0; i < 4; i++) {
        v[i] = *(const float4*)&p[i * 1024 + tid * 4];
        mx = fmaxf(mx, fmaxf(fmaxf(v[i].x, v[i].y), fmaxf(v[i].z, v[i].w)));
    }
    __shared__ float red[8];
#pragma unroll
    for (int off = 16; off; off >>= 1) mx = fmaxf(mx, __shfl_xor_sync(0xffffffffu, mx, off));
    if ((tid & 31) == 0) red[tid >> 5] = mx;
    __syncthreads();
    mx = red[0];
#pragma unroll
    for (int i = 1; i < 8; i++) mx = fmaxf(mx, red[i]);
    __syncthreads();
    float s = 0.f;
#pragma unroll
    for (int i = 0; i < 4; i++) {
        v[i].x = __expf(v[i].x - mx); v[i].y = __expf(v[i].y - mx);
        v[i].z = __expf(v[i].z - mx); v[i].w = __expf(v[i].w - mx);
        s += v[i].x + v[i].y + v[i].z + v[i].w;
    }
#pragma unroll
    for (int off = 16; off; off >>= 1) s += __shfl_xor_sync(0xffffffffu, s, off);
    if ((tid & 31) == 0) red[tid >> 5] = s;
    __syncthreads();
    s = 0.f;
#pragma unroll
    for (int i = 0; i < 8; i++) s += red[i];
    const float inv = 1.f / s;
#pragma unroll
    for (int i = 0; i < 4; i++) {
        __half2* d = (__half2*)&po[i * 1024 + tid * 4];
        d[0] = __floats2half2_rn(v[i].x * inv, v[i].y * inv);
        d[1] = __floats2half2_rn(v[i].z * inv, v[i].w * inv);
    }
}

__global__ void softmax512_cam_kernel(const float* __restrict__ e, __half* __restrict__ o)
{
    const float* p = e + (size_t)blockIdx.x * 512;
    __half* po = o + (size_t)blockIdx.x * 512;
    const int tid = threadIdx.x;
    float4 v = *(const float4*)&p[tid * 4];
    float mn = fminf(fminf(v.x, v.y), fminf(v.z, v.w));
    __shared__ float red[4];
#pragma unroll
    for (int off = 16; off; off >>= 1) mn = fminf(mn, __shfl_xor_sync(0xffffffffu, mn, off));
    if ((tid & 31) == 0) red[tid >> 5] = mn;
    __syncthreads();
    mn = fminf(fminf(red[0], red[1]), fminf(red[2], red[3]));
    __syncthreads();
    v.x = __expf(mn - v.x); v.y = __expf(mn - v.y);
    v.z = __expf(mn - v.z); v.w = __expf(mn - v.w);
    float s = v.x + v.y + v.z + v.w;
#pragma unroll
    for (int off = 16; off; off >>= 1) s += __shfl_xor_sync(0xffffffffu, s, off);
    if ((tid & 31) == 0) red[tid >> 5] = s;
    __syncthreads();
    s = red[0] + red[1] + red[2] + red[3];
    const float inv = 1.f / s;
    __half2* d = (__half2*)&po[tid * 4];
    d[0] = __floats2half2_rn(v.x * inv, v.y * inv);
    d[1] = __floats2half2_rn(v.z * inv, v.w * inv);
}

// ===========================================================================
// Launch
// ===========================================================================
static inline int smg(int al, int bl) {
    int a = (al ? 32 * PKM : 128 * PMK) * 2;
    int b = (bl ? 32 * PKM : 128 * PMK) * 2;
    return 2 * a + 2 * b;
}

extern "C" void kernel_launch(void* const* d_in, const int* in_sizes, int n_in,
                              void* d_out, int out_size)
{
    (void)in_sizes; (void)n_in; (void)out_size;
    const float* x   = (const float*)d_in[0];
    const float* w5a = (const float*)d_in[1];
    const float* w5c = (const float*)d_in[6];
    const float* wq  = (const float*)d_in[11];
    const float* bq  = (const float*)d_in[12];
    const float* wk  = (const float*)d_in[13];
    const float* bk  = (const float*)d_in[14];
    const float* wv  = (const float*)d_in[15];
    const float* bv  = (const float*)d_in[16];
    const float* gpam = (const float*)d_in[17];
    const float* gcam = (const float*)d_in[18];
    const float* w51 = (const float*)d_in[19];
    const float* w52 = (const float*)d_in[24];
    float* out = (float*)d_out;

    __half *xr, *f1h, *f2h, *qh, *kh, *vh, *attnh, *camh, *wa, *wc, *w1, *w2, *wqh, *wkh, *wvh;
    float *energy, *cam, *saf, *scf, *sacv;
    cudaGetSymbolAddress((void**)&xr, g_xr);
    cudaGetSymbolAddress((void**)&f1h, g_feat1h);
    cudaGetSymbolAddress((void**)&f2h, g_feat2h);
    cudaGetSymbolAddress((void**)&qh, g_qh);
    cudaGetSymbolAddress((void**)&kh, g_kh);
    cudaGetSymbolAddress((void**)&vh, g_vh);
    cudaGetSymbolAddress((void**)&attnh, g_attnh);
    cudaGetSymbolAddress((void**)&camh, g_camh);
    cudaGetSymbolAddress((void**)&energy, g_energy);
    cudaGetSymbolAddress((void**)&cam, g_cam);
    cudaGetSymbolAddress((void**)&saf, g_saf);
    cudaGetSymbolAddress((void**)&scf, g_scf);
    cudaGetSymbolAddress((void**)&sacv, g_sacv);
    cudaGetSymbolAddress((void**)&wa, g_wa);
    cudaGetSymbolAddress((void**)&wc, g_wc);
    cudaGetSymbolAddress((void**)&w1, g_w1);
    cudaGetSymbolAddress((void**)&w2, g_w2);
    cudaGetSymbolAddress((void**)&wqh, g_wqh);
    cudaGetSymbolAddress((void**)&wkh, g_wkh);
    cudaGetSymbolAddress((void**)&wvh, g_wvh);

    cudaFuncSetAttribute(conv_px, cudaFuncAttributeMaxDynamicSharedMemorySize, CPX_SM);
    cudaFuncSetAttribute(conv_f16, cudaFuncAttributeMaxDynamicSharedMemorySize, CONV_SM);
    cudaFuncSetAttribute(gemm_f16<0,1,3,1>, cudaFuncAttributeMaxDynamicSharedMemorySize, smg(0,1));
    cudaFuncSetAttribute(gemm_f16<0,1,1,1>, cudaFuncAttributeMaxDynamicSharedMemorySize, smg(0,1));
    cudaFuncSetAttribute(gemm_f16<1,1,0,0>, cudaFuncAttributeMaxDynamicSharedMemorySize, smg(1,1));
    cudaFuncSetAttribute(gemm_f16<0,0,2,0>, cudaFuncAttributeMaxDynamicSharedMemorySize, smg(0,0));
    cudaFuncSetAttribute(gemm_f16<0,0,4,0>, cudaFuncAttributeMaxDynamicSharedMemorySize, smg(0,0));
    cudaFuncSetAttribute(gemm_f16<0,1,2,0>, cudaFuncAttributeMaxDynamicSharedMemorySize, smg(0,1));

    // prep
    transpose_x<<<dim3(64, 128, 2), 256>>>(x, xr);
    f2h_kernel<<<128, 256>>>(wq, wqh, 64 * 512);
    f2h_kernel<<<128, 256>>>(wk, wkh, 64 * 512);
    f2h_kernel<<<1024, 256>>>(wv, wvh, 512 * 512);
    repack_wh<<<dim3(16, 256), 256>>>(w5a, wa, 2048);
    repack_wh<<<dim3(16, 256), 256>>>(w5c, wc, 2048);
    repack_wh<<<dim3(16, 64), 256>>>(w51, w1, 512);
    repack_wh<<<dim3(16, 64), 256>>>(w52, w2, 512);
    fold_bn_kernel<<<4, 512>>>(
        (const float*)d_in[2],  (const float*)d_in[3],  (const float*)d_in[4],  (const float*)d_in[5],
        (const float*)d_in[7],  (const float*)d_in[8],  (const float*)d_in[9],  (const float*)d_in[10],
        (const float*)d_in[20], (const float*)d_in[21], (const float*)d_in[22], (const float*)d_in[23],
        (const float*)d_in[25], (const float*)d_in[26], (const float*)d_in[27], (const float*)d_in[28]);
    zero_cam_kernel<<<512, 256>>>();

    const dim3 cg(4, 32, 2);
    const long F = 512L * 4096, Q = 64L * 4096, E = 4096L * 4096;

    // big convs via pixel-major fast path
    conv_px<<<cg, 256, CPX_SM>>>(xr, wa, 2048, 0, f1h);
    conv_px<<<cg, 256, CPX_SM>>>(xr, wc, 2048, 1, f2h);

    // q,k stacked; v
    gemm_f16<0,1,3,1><<<dim3(1, 32, 2), 256, smg(0,1)>>>(
        wqh, f1h, qh, 512, 4096, 4096, 512, 0, F, Q, wkh, bq, bk, nullptr, nullptr, 0, kh, Q);
    gemm_f16<0,1,1,1><<<dim3(4, 32, 2), 256, smg(0,1)>>>(
        wvh, f1h, vh, 512, 4096, 4096, 512, 0, F, F, nullptr, bv, nullptr, nullptr, nullptr, 0, nullptr, 0);

    // PAM energy, softmax
    gemm_f16<1,1,0,0><<<dim3(32, 32, 2), 256, smg(1,1)>>>(
        qh, kh, energy, 4096, 4096, 4096, 64, Q, Q, E, nullptr, nullptr, nullptr, nullptr, nullptr, 0, nullptr, 0);
    softmax4096_kernel<<<8192, 256>>>(energy, attnh);

    // sa_feat
    gemm_f16<0,0,2,0><<<dim3(4, 32, 2), 256, smg(0,0)>>>(
        vh, attnh, saf, 4096, 4096, 4096, 4096, F, E, F, nullptr, nullptr, nullptr, gpam, f1h, F, nullptr, 0);

    // CAM energy split-K (K=512 per split), softmax
    gemm_f16<0,0,4,0><<<dim3(4, 4, 16), 256, smg(0,0)>>>(
        f2h, f2h, cam, 4096, 4096, 512, 512, F, F, 512L * 512, nullptr, nullptr, nullptr, nullptr, nullptr, 0, nullptr, 0);
    softmax512_cam_kernel<<<1024, 128>>>(cam, camh);

    // sc_feat
    gemm_f16<0,1,2,0><<<dim3(4, 32, 2), 256, smg(0,1)>>>(
        camh, f2h, scf, 512, 4096, 4096, 512, 512L * 512, F, F, nullptr, nullptr, nullptr, gcam, f2h, F, nullptr, 0);

    // small convs (gather path)
    conv_f16<<<cg, 256, CONV_SM>>>(saf, w1, 512, 2, nullptr, sacv);
    conv_f16<<<cg, 256, CONV_SM>>>(scf, w2, 512, 3, sacv, out);
}